// round 1
// baseline (speedup 1.0000x reference)
#include <cuda_runtime.h>
#include <cuda_bf16.h>

// Direct 3x3 conv, pad=1, fp32, NCHW. x[16,64,256,256], W[64,64,3,3], b[64].
// CTA: 256 threads -> tile of 16 oc x 4 h x 64 w. ic staged in blocks of 8.
// Each thread: 4 oc x 4 px accumulators, 3x6 input window in registers.

#define N_IMG 16
#define C_IN 64
#define C_OUT 64
#define H 256
#define WD 256

#define TB_OC 16
#define TB_H 4
#define TB_W 64
#define ICB 8
#define SW 66  // TB_W + 2

__global__ __launch_bounds__(256, 4)
void blindspot_conv_kernel(const float* __restrict__ x,
                           const float* __restrict__ Wt,
                           const float* __restrict__ bias,
                           float* __restrict__ out)
{
    __shared__ float sIn[ICB][TB_H + 2][SW];   // 8*6*66*4 = 12672 B
    __shared__ float sWg[ICB][9][TB_OC];       // 8*9*16*4 = 4608 B

    const int tid = threadIdx.x;
    const int n   = blockIdx.z;
    const int oc0 = blockIdx.y * TB_OC;
    const int ht  = blockIdx.x >> 2;        // 64 h-tiles
    const int wt  = blockIdx.x & 3;         // 4 w-tiles
    const int h0  = ht * TB_H;
    const int w0  = wt * TB_W;

    const int wg = tid & 15;                // 16 w-groups of 4 px
    const int hh = (tid >> 4) & 3;          // row within tile
    const int og = tid >> 6;                // 4 oc-groups of 4 oc

    float acc[4][4];
    #pragma unroll
    for (int o = 0; o < 4; ++o)
        #pragma unroll
        for (int p = 0; p < 4; ++p)
            acc[o][p] = 0.0f;

    for (int icb = 0; icb < C_IN / ICB; ++icb) {
        const int icBase = icb * ICB;

        // ---- stage input halo: 8 ic x 6 rows x 66 cols ----
        for (int i = tid; i < ICB * (TB_H + 2) * SW; i += 256) {
            int ci  = i / ((TB_H + 2) * SW);
            int rem = i - ci * ((TB_H + 2) * SW);
            int r   = rem / SW;
            int c   = rem - r * SW;
            int gh  = h0 - 1 + r;
            int gw  = w0 - 1 + c;
            float v = 0.0f;
            if ((unsigned)gh < (unsigned)H && (unsigned)gw < (unsigned)WD) {
                v = x[(((size_t)n * C_IN + icBase + ci) * H + gh) * WD + gw];
            }
            sIn[ci][r][c] = v;
        }
        // ---- stage weights: 8 ic x 9 taps x 16 oc ----
        for (int i = tid; i < ICB * 9 * TB_OC; i += 256) {
            int ci  = i / (9 * TB_OC);
            int rem = i - ci * (9 * TB_OC);
            int k   = rem / TB_OC;
            int ol  = rem - k * TB_OC;
            sWg[ci][k][ol] = Wt[((size_t)(oc0 + ol) * C_IN + icBase + ci) * 9 + k];
        }
        __syncthreads();

        #pragma unroll
        for (int ci = 0; ci < ICB; ++ci) {
            // input window: rows hh..hh+2, cols wg*4 .. wg*4+5
            float xv[3][6];
            #pragma unroll
            for (int r = 0; r < 3; ++r)
                #pragma unroll
                for (int c = 0; c < 6; ++c)
                    xv[r][c] = sIn[ci][hh + r][wg * 4 + c];

            #pragma unroll
            for (int k = 0; k < 9; ++k) {
                const int kh = k / 3;
                const int kw = k - kh * 3;
                float w4[4];
                #pragma unroll
                for (int o = 0; o < 4; ++o)
                    w4[o] = sWg[ci][k][og * 4 + o];   // warp-uniform broadcast
                #pragma unroll
                for (int o = 0; o < 4; ++o)
                    #pragma unroll
                    for (int p = 0; p < 4; ++p)
                        acc[o][p] = fmaf(xv[kh][p + kw], w4[o], acc[o][p]);
            }
        }
        __syncthreads();
    }

    // ---- epilogue: bias + float4 stores ----
    const int hrow = h0 + hh;
    const int wcol = w0 + wg * 4;
    #pragma unroll
    for (int o = 0; o < 4; ++o) {
        const int oc = oc0 + og * 4 + o;
        const float bv = bias[oc];
        float4 v;
        v.x = acc[o][0] + bv;
        v.y = acc[o][1] + bv;
        v.z = acc[o][2] + bv;
        v.w = acc[o][3] + bv;
        size_t off = (((size_t)n * C_OUT + oc) * H + hrow) * WD + wcol;
        *reinterpret_cast<float4*>(out + off) = v;
    }
}

extern "C" void kernel_launch(void* const* d_in, const int* in_sizes, int n_in,
                              void* d_out, int out_size)
{
    const float* x  = (const float*)d_in[0];
    const float* Wt = (const float*)d_in[1];
    const float* b  = (const float*)d_in[2];
    float* out = (float*)d_out;

    dim3 grid((H / TB_H) * (WD / TB_W),   // 64 * 4 = 256 spatial tiles
              C_OUT / TB_OC,              // 4 oc blocks
              N_IMG);                     // 16 images
    blindspot_conv_kernel<<<grid, 256>>>(x, Wt, b, out);
}

// round 3
// speedup vs baseline: 1.9882x; 1.9882x over previous
#include <cuda_runtime.h>
#include <cstdint>

#define HH 256
#define WW 256

__device__ __forceinline__ uint32_t f2tf32(float f) {
    uint32_t r;
    asm("cvt.rna.tf32.f32 %0, %1;" : "=r"(r) : "f"(f));
    return r;
}

// SMEM layout (floats):
//   sIn[3][16][264]  input rows h-1..h+1, 16-ic chunk, cols 0..257 (= gw -1..256)
//   sW [9][16][72]   weights for chunk: [tap][ic][oc] with oc-stride pad 72
//   sB [64]          bias
#define SIN_SZ (3 * 16 * 264)
#define SW_SZ  (9 * 16 * 72)
#define SMEM_BYTES ((SIN_SZ + SW_SZ + 64) * 4)

__global__ __launch_bounds__(256, 2)
void conv_tf32_mma_kernel(const float* __restrict__ x,
                          const float* __restrict__ Wt,
                          const float* __restrict__ bias,
                          float* __restrict__ out)
{
    extern __shared__ float sm[];
    float* sIn = sm;
    float* sW  = sm + SIN_SZ;
    float* sB  = sm + SIN_SZ + SW_SZ;

    const int tid  = threadIdx.x;
    const int lane = tid & 31;
    const int wid  = tid >> 5;
    const int g    = lane >> 2;   // groupID
    const int tig  = lane & 3;    // thread-in-group
    const int h    = blockIdx.x;
    const int n    = blockIdx.y;
    const int px0  = (wid >> 1) * 64;   // warp M offset (4 warps along M)
    const int oc0  = (wid & 1) * 32;    // warp N offset (2 warps along N)

    if (tid < 64) sB[tid] = bias[tid];

    float c[4][4][4];
    #pragma unroll
    for (int mt = 0; mt < 4; ++mt)
        #pragma unroll
        for (int nt = 0; nt < 4; ++nt)
            #pragma unroll
            for (int r = 0; r < 4; ++r) c[mt][nt][r] = 0.0f;

    for (int chunk = 0; chunk < 4; ++chunk) {
        const int ic0 = chunk * 16;
        if (chunk) __syncthreads();

        // ---- stage input: 3 rows x 16 ic x 258 cols, tf32-rounded ----
        for (int i = tid; i < 3 * 16 * 258; i += 256) {
            int col = i % 258;
            int t2  = i / 258;
            int ic  = t2 % 16;
            int kh  = t2 / 16;
            int gh  = h + kh - 1;
            int gw  = col - 1;
            float v = 0.0f;
            if ((unsigned)gh < 256u && (unsigned)gw < 256u)
                v = x[(((size_t)n * 64 + ic0 + ic) * 256 + gh) * 256 + gw];
            sIn[kh * (16 * 264) + ic * 264 + col] = __uint_as_float(f2tf32(v));
        }
        // ---- stage weights: sW[tap][icl][oc], tf32-rounded ----
        for (int i = tid; i < 9 * 16 * 64; i += 256) {
            int oc  = i & 63;
            int icl = (i >> 6) & 15;
            int tap = i >> 10;
            float v = Wt[(size_t)oc * 576 + (ic0 + icl) * 9 + tap];
            sW[tap * (16 * 72) + icl * 72 + oc] = __uint_as_float(f2tf32(v));
        }
        __syncthreads();

        // ---- compute: 9 taps x 2 k8-steps, warp tile 64x32 ----
        #pragma unroll
        for (int kh = 0; kh < 3; ++kh) {
            #pragma unroll
            for (int kw = 0; kw < 3; ++kw) {
                const float* inB = sIn + kh * (16 * 264);
                const float* wB  = sW + (kh * 3 + kw) * (16 * 72);
                #pragma unroll
                for (int s = 0; s < 2; ++s) {
                    const int icA = s * 8 + tig;
                    uint32_t a[4][4];
                    #pragma unroll
                    for (int mt = 0; mt < 4; ++mt) {
                        const int px = px0 + mt * 16 + g;
                        a[mt][0] = __float_as_uint(inB[icA * 264 + px + kw]);
                        a[mt][1] = __float_as_uint(inB[icA * 264 + px + 8 + kw]);
                        a[mt][2] = __float_as_uint(inB[(icA + 4) * 264 + px + kw]);
                        a[mt][3] = __float_as_uint(inB[(icA + 4) * 264 + px + 8 + kw]);
                    }
                    uint32_t b[4][2];
                    #pragma unroll
                    for (int nt = 0; nt < 4; ++nt) {
                        const int oc = oc0 + nt * 8 + g;
                        b[nt][0] = __float_as_uint(wB[icA * 72 + oc]);
                        b[nt][1] = __float_as_uint(wB[(icA + 4) * 72 + oc]);
                    }
                    #pragma unroll
                    for (int mt = 0; mt < 4; ++mt)
                        #pragma unroll
                        for (int nt = 0; nt < 4; ++nt)
                            asm volatile(
                                "mma.sync.aligned.m16n8k8.row.col.f32.tf32.tf32.f32 "
                                "{%0,%1,%2,%3}, {%4,%5,%6,%7}, {%8,%9}, {%0,%1,%2,%3};"
                                : "+f"(c[mt][nt][0]), "+f"(c[mt][nt][1]),
                                  "+f"(c[mt][nt][2]), "+f"(c[mt][nt][3])
                                : "r"(a[mt][0]), "r"(a[mt][1]),
                                  "r"(a[mt][2]), "r"(a[mt][3]),
                                  "r"(b[nt][0]), "r"(b[nt][1]));
                }
            }
        }
    }

    // ---- epilogue: bias + store (4 full 32B sectors per STG instruction) ----
    #pragma unroll
    for (int mt = 0; mt < 4; ++mt) {
        const int px = px0 + mt * 16 + g;
        #pragma unroll
        for (int nt = 0; nt < 4; ++nt) {
            const int oc = oc0 + nt * 8 + 2 * tig;
            const size_t b0 = (((size_t)n * 64 + oc) * 256 + h) * 256;
            const size_t b1 = (((size_t)n * 64 + oc + 1) * 256 + h) * 256;
            out[b0 + px]     = c[mt][nt][0] + sB[oc];
            out[b1 + px]     = c[mt][nt][1] + sB[oc + 1];
            out[b0 + px + 8] = c[mt][nt][2] + sB[oc];
            out[b1 + px + 8] = c[mt][nt][3] + sB[oc + 1];
        }
    }
}

extern "C" void kernel_launch(void* const* d_in, const int* in_sizes, int n_in,
                              void* d_out, int out_size)
{
    const float* x  = (const float*)d_in[0];
    const float* Wt = (const float*)d_in[1];
    const float* b  = (const float*)d_in[2];
    float* out = (float*)d_out;

    cudaFuncSetAttribute(conv_tf32_mma_kernel,
                         cudaFuncAttributeMaxDynamicSharedMemorySize, SMEM_BYTES);

    dim3 grid(HH, 16);   // (h, n) = 4096 CTAs, M=256 px per CTA
    conv_tf32_mma_kernel<<<grid, 256, SMEM_BYTES>>>(x, Wt, b, out);
}